// round 6
// baseline (speedup 1.0000x reference)
#include <cuda_runtime.h>
#include <cuda_fp16.h>
#include <cstdint>

namespace qef {

constexpr int E_ = 8, T_ = 1024, DIN = 2048, DOUT = 8192;

// -------- scratch, fragment-ordered for mma.m16n8k16 --------
// B: [e][ntile(n/8)=1024][ks16(128)][256B]        (32 lanes x 8B: {b0,b1})
// A: [e][mtile(m/16)=64][ks16(128)][lvl(2)][512B] (32 lanes x 16B: {a0..a3})
__device__ __align__(16) unsigned char g_brep[(size_t)E_ * 1024 * 128 * 256];
__device__ __align__(16) unsigned char g_arep[(size_t)E_ * 64 * 128 * 2 * 512];

__device__ __forceinline__ uint32_t hpack(__half lo, __half hi) {
  return (uint32_t)__half_as_ushort(lo) | ((uint32_t)__half_as_ushort(hi) << 16);
}

// ---------------- repack weights: int32 -> f16 fragments (coalesced) ---------
__global__ void __launch_bounds__(256) repack_b(const int* __restrict__ wq) {
  const int t   = blockIdx.x * 256 + threadIdx.x;   // [0, 2^22)
  const int nlo = t & 7;
  const int kc  = (t >> 3) & 63;
  const int nhi = (t >> 9) & 1023;
  const int e   = t >> 19;
  const int n   = nhi * 8 + nlo;
  const int4* src = reinterpret_cast<const int4*>(
      wq + ((size_t)e * DOUT + n) * DIN + kc * 32);
  int v[32];
#pragma unroll
  for (int i = 0; i < 8; ++i) {
    int4 q = src[i];
    v[i * 4 + 0] = q.x; v[i * 4 + 1] = q.y; v[i * 4 + 2] = q.z; v[i * 4 + 3] = q.w;
  }
#pragma unroll
  for (int s = 0; s < 2; ++s) {
    unsigned char* blk = g_brep +
        ((((size_t)e * 1024 + nhi) * 128 + kc * 2 + s) << 8);
#pragma unroll
    for (int j = 0; j < 4; ++j) {
      const int kb = s * 16 + 2 * j;
      const uint32_t w0 = hpack(__int2half_rn(v[kb]),     __int2half_rn(v[kb + 1]));
      const uint32_t w1 = hpack(__int2half_rn(v[kb + 8]), __int2half_rn(v[kb + 9]));
      *reinterpret_cast<uint2*>(blk + (nlo * 4 + j) * 8) = make_uint2(w0, w1);
    }
  }
}

// ---------------- repack input: fp32 -> hi/lo f16 fragments (coalesced) ------
__global__ void __launch_bounds__(256) repack_a(const float* __restrict__ in) {
  const int t  = blockIdx.x * 256 + threadIdx.x;    // [0, 2^19)
  const int r  = t & 15;
  const int kc = (t >> 4) & 63;
  const int mt = (t >> 10) & 63;
  const int e  = t >> 16;
  const int m  = mt * 16 + r;
  const float4* src = reinterpret_cast<const float4*>(
      in + ((size_t)e * T_ + m) * DIN + kc * 32);
  __half h[32], l[32];
#pragma unroll
  for (int i = 0; i < 8; ++i) {
    float4 x4 = src[i];
    float xs[4] = {x4.x, x4.y, x4.z, x4.w};
#pragma unroll
    for (int c = 0; c < 4; ++c) {
      __half hh = __float2half_rn(xs[c]);
      h[i * 4 + c] = hh;
      l[i * 4 + c] = __float2half_rn(xs[c] - __half2float(hh));
    }
  }
  const uint32_t lbase = (uint32_t)((r & 7) * 4) * 16 + ((r >= 8) ? 4u : 0u);
#pragma unroll
  for (int s = 0; s < 2; ++s) {
#pragma unroll
    for (int lvl = 0; lvl < 2; ++lvl) {
      const __half* vv = lvl ? l : h;
      unsigned char* blk = g_arep +
          (((((size_t)e * 64 + mt) * 128 + kc * 2 + s) * 2 + lvl) << 9);
#pragma unroll
      for (int j = 0; j < 4; ++j) {
        const int kb = s * 16 + 2 * j;
        const uint32_t off = lbase + j * 16;
        *reinterpret_cast<uint32_t*>(blk + off)     = hpack(vv[kb],     vv[kb + 1]);
        *reinterpret_cast<uint32_t*>(blk + off + 8) = hpack(vv[kb + 8], vv[kb + 9]);
      }
    }
  }
}

// ---------------- GEMM: 128x128 CTA, 16 warps (4m x 4n) ----------------------
// hi pass: fp32-acc HMMA ; lo pass: fp16-acc HMMA (partial sums O(10), safe)
constexpr int STAGES = 4;
constexpr int A_STAGE = 8 * 2 * 2 * 512;   // 16KB: [mt(8)][kstep(2)][lvl(2)]x512
constexpr int B_STAGE = 16 * 2 * 256;      // 8KB : [nt(16)][kstep(2)]x256
constexpr int STAGE_BYTES = A_STAGE + B_STAGE;      // 24KB
constexpr int SMEM_TOTAL  = STAGES * STAGE_BYTES;   // 96KB

__device__ __forceinline__ uint32_t cvta_smem(const void* p) {
  uint32_t a;
  asm("{ .reg .u64 t; cvta.to.shared.u64 t, %1; cvt.u32.u64 %0, t; }" : "=r"(a) : "l"(p));
  return a;
}
__device__ __forceinline__ void cp16(uint32_t sdst, const void* gsrc) {
  asm volatile("cp.async.cg.shared.global [%0], [%1], 16;" :: "r"(sdst), "l"(gsrc));
}
__device__ __forceinline__ void cp_commit() {
  asm volatile("cp.async.commit_group;" ::: "memory");
}
__device__ __forceinline__ void cp_wait2() {
  asm volatile("cp.async.wait_group 2;" ::: "memory");
}
__device__ __forceinline__ void lds128(uint32_t* r, uint32_t a) {
  asm volatile("ld.shared.v4.b32 {%0,%1,%2,%3}, [%4];"
               : "=r"(r[0]), "=r"(r[1]), "=r"(r[2]), "=r"(r[3]) : "r"(a));
}
__device__ __forceinline__ void lds64(uint32_t* r, uint32_t a) {
  asm volatile("ld.shared.v2.b32 {%0,%1}, [%2];" : "=r"(r[0]), "=r"(r[1]) : "r"(a));
}
__device__ __forceinline__ void hmma_f32(float* d, const uint32_t* a, const uint32_t* b) {
  asm volatile(
      "mma.sync.aligned.m16n8k16.row.col.f32.f16.f16.f32 "
      "{%0,%1,%2,%3}, {%4,%5,%6,%7}, {%8,%9}, {%0,%1,%2,%3};"
      : "+f"(d[0]), "+f"(d[1]), "+f"(d[2]), "+f"(d[3])
      : "r"(a[0]), "r"(a[1]), "r"(a[2]), "r"(a[3]), "r"(b[0]), "r"(b[1]));
}
__device__ __forceinline__ void hmma_f16(uint32_t* d, const uint32_t* a, const uint32_t* b) {
  asm volatile(
      "mma.sync.aligned.m16n8k16.row.col.f16.f16.f16.f16 "
      "{%0,%1}, {%2,%3,%4,%5}, {%6,%7}, {%0,%1};"
      : "+r"(d[0]), "+r"(d[1])
      : "r"(a[0]), "r"(a[1]), "r"(a[2]), "r"(a[3]), "r"(b[0]), "r"(b[1]));
}

__global__ void __launch_bounds__(512, 1)
gemm(const float* __restrict__ sc, float* __restrict__ out) {
  extern __shared__ unsigned char smem[];
  const uint32_t sbase = cvta_smem(smem);
  const int tid  = threadIdx.x;
  const int wid  = tid >> 5;
  const int lane = tid & 31;

  const int bid = blockIdx.x;
  const int e   = bid >> 9;
  const int m   = bid & 7;          // 8 m-tiles of 128 (fast: co-resident share B)
  const int n   = (bid >> 3) & 63;  // 64 n-tiles of 128

  const int wm = wid & 3;           // 4 x 32 rows
  const int wn = wid >> 2;          // 4 x 32 cols

  const unsigned char* abase = g_arep + (size_t)(e * 64 + m * 8) * 128 * 2 * 512;
  const unsigned char* bbase = g_brep + (size_t)(e * 1024 + n * 16) * 128 * 256;

  // per-thread cp.async pointers (increment per stage; no per-stage index ALU)
  // A: 1024 units/stage (u = tid, tid+512); B: 512 units/stage (v = tid)
  auto a_ptr = [&](int u) {
    const int chunk = u >> 5, pos = u & 31;          // chunk = mt*4+kstep*2+lvl
    const int mt = chunk >> 2, kstep = (chunk >> 1) & 1, lvl = chunk & 1;
    return abase + (size_t)mt * 131072 + kstep * 1024 + lvl * 512 + pos * 16;
  };
  const unsigned char* pa0 = a_ptr(tid);
  const unsigned char* pa1 = a_ptr(tid + 512);
  const unsigned char* pb;
  {
    const int chunk = tid >> 4, pos = tid & 15;      // chunk = nt*2+kstep
    const int nt = chunk >> 1, kstep = chunk & 1;
    pb = bbase + (size_t)nt * 32768 + kstep * 256 + pos * 16;
  }
  const uint32_t sA0 = tid * 16;
  const uint32_t sA1 = (tid + 512) * 16;
  const uint32_t sB  = A_STAGE + tid * 16;

  auto issue_stage = [&](int st) {
    const uint32_t sb = sbase + st * STAGE_BYTES;
    cp16(sb + sA0, pa0);
    cp16(sb + sA1, pa1);
    cp16(sb + sB,  pb);
    cp_commit();
    pa0 += 2048; pa1 += 2048; pb += 512;   // advance 2 k16-steps
  };

  float    acch[2][4][4];
  uint32_t accl[2][4][2];
#pragma unroll
  for (int mi = 0; mi < 2; ++mi)
#pragma unroll
    for (int ni = 0; ni < 4; ++ni) {
#pragma unroll
      for (int c = 0; c < 4; ++c) acch[mi][ni][c] = 0.0f;
      accl[mi][ni][0] = 0u; accl[mi][ni][1] = 0u;
    }

  const int NKS = 64;   // 64 stages of K=32
  issue_stage(0);
  issue_stage(1);
  issue_stage(2);

  for (int ks = 0; ks < NKS; ++ks) {
    cp_wait2();
    __syncthreads();
    const uint32_t sb = sbase + (ks & 3) * STAGE_BYTES;
#pragma unroll
    for (int kstep = 0; kstep < 2; ++kstep) {
      uint32_t afh[2][4], afl[2][4], bf[4][2];
#pragma unroll
      for (int mi = 0; mi < 2; ++mi) {
        const uint32_t base =
            sb + ((wm * 2 + mi) * 2 + kstep) * 1024 + lane * 16;
        lds128(afh[mi], base);          // lvl 0 (hi)
        lds128(afl[mi], base + 512);    // lvl 1 (lo)
      }
#pragma unroll
      for (int ni = 0; ni < 4; ++ni)
        lds64(bf[ni], sb + A_STAGE + ((wn * 4 + ni) * 2 + kstep) * 256 + lane * 8);
#pragma unroll
      for (int mi = 0; mi < 2; ++mi)
#pragma unroll
        for (int ni = 0; ni < 4; ++ni) {
          hmma_f32(acch[mi][ni], afh[mi], bf[ni]);
          hmma_f16(accl[mi][ni], afl[mi], bf[ni]);
        }
    }
    // uniform commit: keeps wait_group accounting valid through the tail
    if (ks + 3 < NKS) issue_stage((ks + 3) & 3);
    else              cp_commit();
  }

  // ---- epilogue: out = s * (acc_hi + acc_lo) ----
  const float s = sc[e];
  const int r_in = lane >> 2;
  const int c_in = (lane & 3) * 2;
#pragma unroll
  for (int mi = 0; mi < 2; ++mi) {
    const int row0 = m * 128 + wm * 32 + mi * 16 + r_in;
#pragma unroll
    for (int ni = 0; ni < 4; ++ni) {
      const int col = n * 128 + wn * 32 + ni * 8 + c_in;
      const float* h = acch[mi][ni];
      float2 l01 = __half22float2(*reinterpret_cast<const __half2*>(&accl[mi][ni][0]));
      float2 l23 = __half22float2(*reinterpret_cast<const __half2*>(&accl[mi][ni][1]));
      float* o0 = out + ((size_t)e * T_ + row0) * DOUT + col;
      *reinterpret_cast<float2*>(o0) =
          make_float2((h[0] + l01.x) * s, (h[1] + l01.y) * s);
      *reinterpret_cast<float2*>(o0 + 8 * DOUT) =
          make_float2((h[2] + l23.x) * s, (h[3] + l23.y) * s);
    }
  }
}

}  // namespace qef

extern "C" void kernel_launch(void* const* d_in, const int* in_sizes, int n_in,
                              void* d_out, int out_size) {
  const float* in  = (const float*)d_in[0];
  const int*   wq  = (const int*)d_in[1];
  const float* sc  = (const float*)d_in[2];
  float*       out = (float*)d_out;

  qef::repack_b<<<(8 * 8192 * 64) / 256, 256>>>(wq);
  qef::repack_a<<<(8 * 1024 * 64) / 256, 256>>>(in);

  static bool attr_set = false;
  if (!attr_set) {
    cudaFuncSetAttribute(qef::gemm, cudaFuncAttributeMaxDynamicSharedMemorySize,
                         qef::SMEM_TOTAL);
    attr_set = true;
  }
  qef::gemm<<<8 * 8 * 64, 512, qef::SMEM_TOTAL>>>(sc, out);
}

// round 7
// speedup vs baseline: 1.1973x; 1.1973x over previous
#include <cuda_runtime.h>
#include <cuda_fp16.h>
#include <cstdint>

namespace qef {

constexpr int E_ = 8, T_ = 1024, DIN = 2048, DOUT = 8192;

// -------- scratch, fragment-ordered for mma.m16n8k16 --------
// B: [e][ntile(n/8)=1024][ks16(128)][256B]        (32 lanes x 8B: {b0,b1})
// A: [e][mtile(m/16)=64][ks16(128)][lvl(2)][512B] (32 lanes x 16B: {a0..a3})
__device__ __align__(16) unsigned char g_brep[(size_t)E_ * 1024 * 128 * 256];
__device__ __align__(16) unsigned char g_arep[(size_t)E_ * 64 * 128 * 2 * 512];

__device__ __forceinline__ uint32_t hpack(__half lo, __half hi) {
  return (uint32_t)__half_as_ushort(lo) | ((uint32_t)__half_as_ushort(hi) << 16);
}

// ---------------- repack weights: int32 -> f16 fragments (coalesced) ---------
__global__ void __launch_bounds__(256) repack_b(const int* __restrict__ wq) {
  const int t   = blockIdx.x * 256 + threadIdx.x;   // [0, 2^22)
  const int nlo = t & 7;
  const int kc  = (t >> 3) & 63;
  const int nhi = (t >> 9) & 1023;
  const int e   = t >> 19;
  const int n   = nhi * 8 + nlo;
  const int4* src = reinterpret_cast<const int4*>(
      wq + ((size_t)e * DOUT + n) * DIN + kc * 32);
  int v[32];
#pragma unroll
  for (int i = 0; i < 8; ++i) {
    int4 q = src[i];
    v[i * 4 + 0] = q.x; v[i * 4 + 1] = q.y; v[i * 4 + 2] = q.z; v[i * 4 + 3] = q.w;
  }
#pragma unroll
  for (int s = 0; s < 2; ++s) {
    unsigned char* blk = g_brep +
        ((((size_t)e * 1024 + nhi) * 128 + kc * 2 + s) << 8);
#pragma unroll
    for (int j = 0; j < 4; ++j) {
      const int kb = s * 16 + 2 * j;
      const uint32_t w0 = hpack(__int2half_rn(v[kb]),     __int2half_rn(v[kb + 1]));
      const uint32_t w1 = hpack(__int2half_rn(v[kb + 8]), __int2half_rn(v[kb + 9]));
      *reinterpret_cast<uint2*>(blk + (nlo * 4 + j) * 8) = make_uint2(w0, w1);
    }
  }
}

// ---------------- repack input: fp32 -> hi/lo f16 fragments (coalesced) ------
__global__ void __launch_bounds__(256) repack_a(const float* __restrict__ in) {
  const int t  = blockIdx.x * 256 + threadIdx.x;    // [0, 2^19)
  const int r  = t & 15;
  const int kc = (t >> 4) & 63;
  const int mt = (t >> 10) & 63;
  const int e  = t >> 16;
  const int m  = mt * 16 + r;
  const float4* src = reinterpret_cast<const float4*>(
      in + ((size_t)e * T_ + m) * DIN + kc * 32);
  __half h[32], l[32];
#pragma unroll
  for (int i = 0; i < 8; ++i) {
    float4 x4 = src[i];
    float xs[4] = {x4.x, x4.y, x4.z, x4.w};
#pragma unroll
    for (int c = 0; c < 4; ++c) {
      __half hh = __float2half_rn(xs[c]);
      h[i * 4 + c] = hh;
      l[i * 4 + c] = __float2half_rn(xs[c] - __half2float(hh));
    }
  }
  const uint32_t lbase = (uint32_t)((r & 7) * 4) * 16 + ((r >= 8) ? 4u : 0u);
#pragma unroll
  for (int s = 0; s < 2; ++s) {
#pragma unroll
    for (int lvl = 0; lvl < 2; ++lvl) {
      const __half* vv = lvl ? l : h;
      unsigned char* blk = g_arep +
          (((((size_t)e * 64 + mt) * 128 + kc * 2 + s) * 2 + lvl) << 9);
#pragma unroll
      for (int j = 0; j < 4; ++j) {
        const int kb = s * 16 + 2 * j;
        const uint32_t off = lbase + j * 16;
        *reinterpret_cast<uint32_t*>(blk + off)     = hpack(vv[kb],     vv[kb + 1]);
        *reinterpret_cast<uint32_t*>(blk + off + 8) = hpack(vv[kb + 8], vv[kb + 9]);
      }
    }
  }
}

// -------- GEMM: CTA 128x256, 8 warps (2m x 4n), warp tile 64x64 --------------
// hi+lo passes both accumulate into ONE fp32 accumulator (k-doubling view).
constexpr int STAGES = 4;
constexpr int A_STAGE = 8 * 2 * 2 * 512;    // 16KB: [mt(8)][kstep(2)][lvl(2)]x512
constexpr int B_STAGE = 32 * 2 * 256;       // 16KB: [nt(32)][kstep(2)]x256
constexpr int STAGE_BYTES = A_STAGE + B_STAGE;      // 32KB
constexpr int SMEM_TOTAL  = STAGES * STAGE_BYTES;   // 128KB

__device__ __forceinline__ uint32_t cvta_smem(const void* p) {
  uint32_t a;
  asm("{ .reg .u64 t; cvta.to.shared.u64 t, %1; cvt.u32.u64 %0, t; }" : "=r"(a) : "l"(p));
  return a;
}
__device__ __forceinline__ void cp16(uint32_t sdst, const void* gsrc) {
  asm volatile("cp.async.cg.shared.global [%0], [%1], 16;" :: "r"(sdst), "l"(gsrc));
}
__device__ __forceinline__ void cp_commit() {
  asm volatile("cp.async.commit_group;" ::: "memory");
}
__device__ __forceinline__ void cp_wait2() {
  asm volatile("cp.async.wait_group 2;" ::: "memory");
}
__device__ __forceinline__ void lds128(uint32_t* r, uint32_t a) {
  asm volatile("ld.shared.v4.b32 {%0,%1,%2,%3}, [%4];"
               : "=r"(r[0]), "=r"(r[1]), "=r"(r[2]), "=r"(r[3]) : "r"(a));
}
__device__ __forceinline__ void lds64(uint32_t* r, uint32_t a) {
  asm volatile("ld.shared.v2.b32 {%0,%1}, [%2];" : "=r"(r[0]), "=r"(r[1]) : "r"(a));
}
__device__ __forceinline__ void hmma_f32(float* d, const uint32_t* a, const uint32_t* b) {
  asm volatile(
      "mma.sync.aligned.m16n8k16.row.col.f32.f16.f16.f32 "
      "{%0,%1,%2,%3}, {%4,%5,%6,%7}, {%8,%9}, {%0,%1,%2,%3};"
      : "+f"(d[0]), "+f"(d[1]), "+f"(d[2]), "+f"(d[3])
      : "r"(a[0]), "r"(a[1]), "r"(a[2]), "r"(a[3]), "r"(b[0]), "r"(b[1]));
}

__global__ void __launch_bounds__(256, 1)
gemm(const float* __restrict__ sc, float* __restrict__ out) {
  extern __shared__ unsigned char smem[];
  const uint32_t sbase = cvta_smem(smem);
  const int tid  = threadIdx.x;
  const int wid  = tid >> 5;
  const int lane = tid & 31;

  const int bid = blockIdx.x;         // ((e*32 + n)*8 + m)
  const int m   = bid & 7;            // 8 m-tiles of 128 (fast: share B in L2)
  const int n   = (bid >> 3) & 31;    // 32 n-tiles of 256
  const int e   = bid >> 8;

  const int wm = wid >> 2;            // 2 x 64 rows
  const int wn = wid & 3;             // 4 x 64 cols

  const unsigned char* abase = g_arep + (size_t)(e * 64 + m * 8) * 131072;
  const unsigned char* bbase = g_brep + (size_t)(e * 1024 + n * 32) * 32768;

  // cp.async: per-thread affine addressing. Unit = 16B; per stage A:1024, B:1024
  // units handled as 4 iterations of 256 threads each; iteration stride is
  // linear in both gmem (262144B) and smem (4096B).
  const unsigned char* pa;
  {
    const int chunk = tid >> 5;                    // mt(0..1)*4 + kstep*2 + lvl
    const int mt = chunk >> 2, kstep = (chunk >> 1) & 1, lvl = chunk & 1;
    pa = abase + (size_t)mt * 131072 + kstep * 1024 + lvl * 512 + (tid & 31) * 16;
  }
  const unsigned char* pb;
  {
    const int chunk = tid >> 4;                    // nt(0..7)*2 + kstep
    const int nt = chunk >> 1, kstep = chunk & 1;
    pb = bbase + (size_t)nt * 32768 + kstep * 256 + (tid & 15) * 16;
  }
  const uint32_t sA0 = tid * 16;
  const uint32_t sB0 = A_STAGE + tid * 16;

  auto issue_stage = [&](int st) {
    const uint32_t sb = sbase + st * STAGE_BYTES;
#pragma unroll
    for (int i = 0; i < 4; ++i) {
      cp16(sb + sA0 + i * 4096, pa + (size_t)i * 262144);
      cp16(sb + sB0 + i * 4096, pb + (size_t)i * 262144);
    }
    cp_commit();
    pa += 2048; pb += 512;            // advance 2 k16-steps
  };

  float acc[4][8][4];
#pragma unroll
  for (int mi = 0; mi < 4; ++mi)
#pragma unroll
    for (int ni = 0; ni < 8; ++ni)
#pragma unroll
      for (int c = 0; c < 4; ++c) acc[mi][ni][c] = 0.0f;

  const int NKS = 64;   // 64 stages of K=32
  issue_stage(0);
  issue_stage(1);
  issue_stage(2);

  for (int ks = 0; ks < NKS; ++ks) {
    cp_wait2();
    __syncthreads();
    const uint32_t sb = sbase + (ks & 3) * STAGE_BYTES;
#pragma unroll
    for (int kstep = 0; kstep < 2; ++kstep) {
      uint32_t afh[4][4], afl[4][4], bf[8][2];
#pragma unroll
      for (int mi = 0; mi < 4; ++mi) {
        const uint32_t base =
            sb + ((wm * 4 + mi) * 2 + kstep) * 1024 + lane * 16;
        lds128(afh[mi], base);          // lvl 0 (hi)
        lds128(afl[mi], base + 512);    // lvl 1 (lo)
      }
#pragma unroll
      for (int ni = 0; ni < 8; ++ni)
        lds64(bf[ni], sb + A_STAGE + ((wn * 8 + ni) * 2 + kstep) * 256 + lane * 8);
#pragma unroll
      for (int mi = 0; mi < 4; ++mi)
#pragma unroll
        for (int ni = 0; ni < 8; ++ni) {
          hmma_f32(acc[mi][ni], afh[mi], bf[ni]);
          hmma_f32(acc[mi][ni], afl[mi], bf[ni]);
        }
    }
    // uniform commit keeps wait_group accounting valid through the tail
    if (ks + 3 < NKS) issue_stage((ks + 3) & 3);
    else              cp_commit();
  }

  // ---- epilogue: out = s * acc ----
  const float s = sc[e];
  const int r_in = lane >> 2;
  const int c_in = (lane & 3) * 2;
#pragma unroll
  for (int mi = 0; mi < 4; ++mi) {
    const int row0 = m * 128 + wm * 64 + mi * 16 + r_in;
#pragma unroll
    for (int ni = 0; ni < 8; ++ni) {
      const int col = n * 256 + wn * 64 + ni * 8 + c_in;
      const float* a = acc[mi][ni];
      float* o0 = out + ((size_t)e * T_ + row0) * DOUT + col;
      *reinterpret_cast<float2*>(o0)            = make_float2(a[0] * s, a[1] * s);
      *reinterpret_cast<float2*>(o0 + 8 * DOUT) = make_float2(a[2] * s, a[3] * s);
    }
  }
}

}  // namespace qef

extern "C" void kernel_launch(void* const* d_in, const int* in_sizes, int n_in,
                              void* d_out, int out_size) {
  const float* in  = (const float*)d_in[0];
  const int*   wq  = (const int*)d_in[1];
  const float* sc  = (const float*)d_in[2];
  float*       out = (float*)d_out;

  qef::repack_b<<<(8 * 8192 * 64) / 256, 256>>>(wq);
  qef::repack_a<<<(8 * 1024 * 64) / 256, 256>>>(in);

  static bool attr_set = false;
  if (!attr_set) {
    cudaFuncSetAttribute(qef::gemm, cudaFuncAttributeMaxDynamicSharedMemorySize,
                         qef::SMEM_TOTAL);
    attr_set = true;
  }
  qef::gemm<<<8 * 32 * 8, 256, qef::SMEM_TOTAL>>>(sc, out);
}

// round 8
// speedup vs baseline: 1.8884x; 1.5773x over previous
#include <cuda_runtime.h>
#include <cuda_fp16.h>
#include <cstdint>

namespace qef {

constexpr int E_ = 8, T_ = 1024, DIN = 2048, DOUT = 8192;

// -------- scratch, fragment-ordered for mma.m16n8k16 --------
// B: [e][ntile(n/8)=1024][ks16(128)][256B]  (32 lanes x 8B: {b0,b1})
// A: [e][mtile(m/16)=64][ks16(128)][512B]   (32 lanes x 16B: {a0..a3})
__device__ __align__(16) unsigned char g_brep[(size_t)E_ * 1024 * 128 * 256];
__device__ __align__(16) unsigned char g_arep[(size_t)E_ * 64 * 128 * 512];

__device__ __forceinline__ uint32_t hpack(__half lo, __half hi) {
  return (uint32_t)__half_as_ushort(lo) | ((uint32_t)__half_as_ushort(hi) << 16);
}

// ---------------- repack weights: int32 -> f16 fragments (coalesced) ---------
__global__ void __launch_bounds__(256) repack_b(const int* __restrict__ wq) {
  const int t   = blockIdx.x * 256 + threadIdx.x;   // [0, 2^22)
  const int nlo = t & 7;
  const int kc  = (t >> 3) & 63;
  const int nhi = (t >> 9) & 1023;
  const int e   = t >> 19;
  const int n   = nhi * 8 + nlo;
  const int4* src = reinterpret_cast<const int4*>(
      wq + ((size_t)e * DOUT + n) * DIN + kc * 32);
  int v[32];
#pragma unroll
  for (int i = 0; i < 8; ++i) {
    int4 q = src[i];
    v[i * 4 + 0] = q.x; v[i * 4 + 1] = q.y; v[i * 4 + 2] = q.z; v[i * 4 + 3] = q.w;
  }
#pragma unroll
  for (int s = 0; s < 2; ++s) {
    unsigned char* blk = g_brep +
        ((((size_t)e * 1024 + nhi) * 128 + kc * 2 + s) << 8);
#pragma unroll
    for (int j = 0; j < 4; ++j) {
      const int kb = s * 16 + 2 * j;
      const uint32_t w0 = hpack(__int2half_rn(v[kb]),     __int2half_rn(v[kb + 1]));
      const uint32_t w1 = hpack(__int2half_rn(v[kb + 8]), __int2half_rn(v[kb + 9]));
      *reinterpret_cast<uint2*>(blk + (nlo * 4 + j) * 8) = make_uint2(w0, w1);
    }
  }
}

// ---------------- repack input: fp32 -> f16 fragments (coalesced) ------------
__global__ void __launch_bounds__(256) repack_a(const float* __restrict__ in) {
  const int t  = blockIdx.x * 256 + threadIdx.x;    // [0, 2^19)
  const int r  = t & 15;
  const int kc = (t >> 4) & 63;
  const int mt = (t >> 10) & 63;
  const int e  = t >> 16;
  const int m  = mt * 16 + r;
  const float4* src = reinterpret_cast<const float4*>(
      in + ((size_t)e * T_ + m) * DIN + kc * 32);
  __half h[32];
#pragma unroll
  for (int i = 0; i < 8; ++i) {
    float4 x4 = src[i];
    h[i * 4 + 0] = __float2half_rn(x4.x);
    h[i * 4 + 1] = __float2half_rn(x4.y);
    h[i * 4 + 2] = __float2half_rn(x4.z);
    h[i * 4 + 3] = __float2half_rn(x4.w);
  }
  const uint32_t lbase = (uint32_t)((r & 7) * 4) * 16 + ((r >= 8) ? 4u : 0u);
#pragma unroll
  for (int s = 0; s < 2; ++s) {
    unsigned char* blk = g_arep +
        ((((size_t)e * 64 + mt) * 128 + kc * 2 + s) << 9);
#pragma unroll
    for (int j = 0; j < 4; ++j) {
      const int kb = s * 16 + 2 * j;
      const uint32_t off = lbase + j * 16;
      *reinterpret_cast<uint32_t*>(blk + off)     = hpack(h[kb],     h[kb + 1]);
      *reinterpret_cast<uint32_t*>(blk + off + 8) = hpack(h[kb + 8], h[kb + 9]);
    }
  }
}

// -------- GEMM: CTA 128x256, 8 warps (2m x 4n), warp tile 64x64, single pass -
constexpr int STAGES = 4;
constexpr int A_STAGE = 8 * 2 * 512;       // 8KB : [mt(8)][kstep(2)] x 512B
constexpr int B_STAGE = 32 * 2 * 256;      // 16KB: [nt(32)][kstep(2)] x 256B
constexpr int STAGE_BYTES = A_STAGE + B_STAGE;      // 24KB
constexpr int SMEM_TOTAL  = STAGES * STAGE_BYTES;   // 96KB

__device__ __forceinline__ uint32_t cvta_smem(const void* p) {
  uint32_t a;
  asm("{ .reg .u64 t; cvta.to.shared.u64 t, %1; cvt.u32.u64 %0, t; }" : "=r"(a) : "l"(p));
  return a;
}
__device__ __forceinline__ void cp16(uint32_t sdst, const void* gsrc) {
  asm volatile("cp.async.cg.shared.global [%0], [%1], 16;" :: "r"(sdst), "l"(gsrc));
}
__device__ __forceinline__ void cp_commit() {
  asm volatile("cp.async.commit_group;" ::: "memory");
}
__device__ __forceinline__ void cp_wait2() {
  asm volatile("cp.async.wait_group 2;" ::: "memory");
}
__device__ __forceinline__ void lds128(uint32_t* r, uint32_t a) {
  asm volatile("ld.shared.v4.b32 {%0,%1,%2,%3}, [%4];"
               : "=r"(r[0]), "=r"(r[1]), "=r"(r[2]), "=r"(r[3]) : "r"(a));
}
__device__ __forceinline__ void lds64(uint32_t* r, uint32_t a) {
  asm volatile("ld.shared.v2.b32 {%0,%1}, [%2];" : "=r"(r[0]), "=r"(r[1]) : "r"(a));
}
__device__ __forceinline__ void hmma_f32(float* d, const uint32_t* a, const uint32_t* b) {
  asm volatile(
      "mma.sync.aligned.m16n8k16.row.col.f32.f16.f16.f32 "
      "{%0,%1,%2,%3}, {%4,%5,%6,%7}, {%8,%9}, {%0,%1,%2,%3};"
      : "+f"(d[0]), "+f"(d[1]), "+f"(d[2]), "+f"(d[3])
      : "r"(a[0]), "r"(a[1]), "r"(a[2]), "r"(a[3]), "r"(b[0]), "r"(b[1]));
}

__global__ void __launch_bounds__(256, 1)
gemm(const float* __restrict__ sc, float* __restrict__ out) {
  extern __shared__ unsigned char smem[];
  const uint32_t sbase = cvta_smem(smem);
  const int tid  = threadIdx.x;
  const int wid  = tid >> 5;
  const int lane = tid & 31;

  const int bid = blockIdx.x;         // ((e*32 + n)*8 + m)
  const int m   = bid & 7;            // 8 m-tiles of 128 (fast: share B in L2)
  const int n   = (bid >> 3) & 31;    // 32 n-tiles of 256
  const int e   = bid >> 8;

  const int wm = wid >> 2;            // 2 x 64 rows
  const int wn = wid & 3;             // 4 x 64 cols

  const unsigned char* abase = g_arep + (size_t)(e * 64 + m * 8) * 65536;
  const unsigned char* bbase = g_brep + (size_t)(e * 1024 + n * 32) * 32768;

  // cp.async per-thread affine addressing; unit = 16B.
  // A: 512 units/stage (2 iters), B: 1024 units/stage (4 iters);
  // iteration stride: gmem +262144B, smem +4096B for both.
  const unsigned char* pa;
  {
    const int chunk = tid >> 5;                    // mt(0..3)*2 + kstep
    const int mt = chunk >> 1, kstep = chunk & 1;
    pa = abase + (size_t)mt * 65536 + kstep * 512 + (tid & 31) * 16;
  }
  const unsigned char* pb;
  {
    const int chunk = tid >> 4;                    // nt(0..7)*2 + kstep
    const int nt = chunk >> 1, kstep = chunk & 1;
    pb = bbase + (size_t)nt * 32768 + kstep * 256 + (tid & 15) * 16;
  }
  const uint32_t sA0 = tid * 16;
  const uint32_t sB0 = A_STAGE + tid * 16;

  auto issue_stage = [&](int st) {
    const uint32_t sb = sbase + st * STAGE_BYTES;
#pragma unroll
    for (int i = 0; i < 2; ++i)
      cp16(sb + sA0 + i * 4096, pa + (size_t)i * 262144);
#pragma unroll
    for (int i = 0; i < 4; ++i)
      cp16(sb + sB0 + i * 4096, pb + (size_t)i * 262144);
    cp_commit();
    pa += 1024; pb += 512;            // advance 2 k16-steps
  };

  float acc[4][8][4];
#pragma unroll
  for (int mi = 0; mi < 4; ++mi)
#pragma unroll
    for (int ni = 0; ni < 8; ++ni)
#pragma unroll
      for (int c = 0; c < 4; ++c) acc[mi][ni][c] = 0.0f;

  const int NKS = 64;   // 64 stages of K=32
  issue_stage(0);
  issue_stage(1);
  issue_stage(2);

  for (int ks = 0; ks < NKS; ++ks) {
    cp_wait2();
    __syncthreads();
    const uint32_t sb = sbase + (ks & 3) * STAGE_BYTES;
#pragma unroll
    for (int kstep = 0; kstep < 2; ++kstep) {
      uint32_t af[4][4], bf[8][2];
#pragma unroll
      for (int mi = 0; mi < 4; ++mi)
        lds128(af[mi], sb + ((wm * 4 + mi) * 2 + kstep) * 512 + lane * 16);
#pragma unroll
      for (int ni = 0; ni < 8; ++ni)
        lds64(bf[ni], sb + A_STAGE + ((wn * 8 + ni) * 2 + kstep) * 256 + lane * 8);
#pragma unroll
      for (int mi = 0; mi < 4; ++mi)
#pragma unroll
        for (int ni = 0; ni < 8; ++ni)
          hmma_f32(acc[mi][ni], af[mi], bf[ni]);
    }
    // uniform commit keeps wait_group accounting valid through the tail
    if (ks + 3 < NKS) issue_stage((ks + 3) & 3);
    else              cp_commit();
  }

  // ---- epilogue: out = s * acc ----
  const float s = sc[e];
  const int r_in = lane >> 2;
  const int c_in = (lane & 3) * 2;
#pragma unroll
  for (int mi = 0; mi < 4; ++mi) {
    const int row0 = m * 128 + wm * 64 + mi * 16 + r_in;
#pragma unroll
    for (int ni = 0; ni < 8; ++ni) {
      const int col = n * 256 + wn * 64 + ni * 8 + c_in;
      const float* a = acc[mi][ni];
      float* o0 = out + ((size_t)e * T_ + row0) * DOUT + col;
      *reinterpret_cast<float2*>(o0)            = make_float2(a[0] * s, a[1] * s);
      *reinterpret_cast<float2*>(o0 + 8 * DOUT) = make_float2(a[2] * s, a[3] * s);
    }
  }
}

}  // namespace qef

extern "C" void kernel_launch(void* const* d_in, const int* in_sizes, int n_in,
                              void* d_out, int out_size) {
  const float* in  = (const float*)d_in[0];
  const int*   wq  = (const int*)d_in[1];
  const float* sc  = (const float*)d_in[2];
  float*       out = (float*)d_out;

  qef::repack_b<<<(8 * 8192 * 64) / 256, 256>>>(wq);
  qef::repack_a<<<(8 * 1024 * 64) / 256, 256>>>(in);

  static bool attr_set = false;
  if (!attr_set) {
    cudaFuncSetAttribute(qef::gemm, cudaFuncAttributeMaxDynamicSharedMemorySize,
                         qef::SMEM_TOTAL);
    attr_set = true;
  }
  qef::gemm<<<8 * 32 * 8, 256, qef::SMEM_TOTAL>>>(sc, out);
}